// round 9
// baseline (speedup 1.0000x reference)
#include <cuda_runtime.h>
#include <cuda_fp16.h>
#include <cstdint>

// ===================== device scratch (allocation-free) =====================
__device__ __half g_xh[8192u * 1024u];
__device__ __half g_xl[8192u * 1024u];
__device__ __half g_hh[8192u * 4096u];   // [h1|h2] hi (fp16)
__device__ __half g_hl[8192u * 4096u];   // [h1|h2] lo (fp16)
__device__ __half g_B1h[4096u * 1024u];  // [W1_1|W2_1]^T hi  [4096,1024]
__device__ __half g_B1l[4096u * 1024u];
__device__ __half g_B2h[384u * 4096u];   // [W2_2^T ; W1_2^T ; 0]  [384,4096]
__device__ __half g_B2l[384u * 4096u];
__device__ float g_part[4u * 8192u * 384u];  // split-K partials

// ===================== PTX helpers (plain sm_80-era PTX only) ==============
__device__ __forceinline__ uint32_t s2u(const void* p) {
    uint32_t a;
    asm("{ .reg .u64 t; cvta.to.shared.u64 t, %1; cvt.u32.u64 %0, t; }" : "=r"(a) : "l"(p));
    return a;
}
__device__ __forceinline__ void cpa16(uint32_t d, const void* s) {
    asm volatile("cp.async.cg.shared.global [%0], [%1], 16;" :: "r"(d), "l"(s));
}
__device__ __forceinline__ void ldsm4(uint32_t* r, uint32_t a) {
    asm volatile("ldmatrix.sync.aligned.m8n8.x4.shared.b16 {%0,%1,%2,%3}, [%4];"
                 : "=r"(r[0]), "=r"(r[1]), "=r"(r[2]), "=r"(r[3]) : "r"(a));
}
__device__ __forceinline__ void mma16816(float* c, const uint32_t* a, const uint32_t* b) {
    asm volatile(
        "mma.sync.aligned.m16n8k16.row.col.f32.f16.f16.f32 "
        "{%0,%1,%2,%3}, {%4,%5,%6,%7}, {%8,%9}, {%0,%1,%2,%3};"
        : "+f"(c[0]), "+f"(c[1]), "+f"(c[2]), "+f"(c[3])
        : "r"(a[0]), "r"(a[1]), "r"(a[2]), "r"(a[3]), "r"(b[0]), "r"(b[1]));
}
// f16-accumulate variant (possible 2x rate vs f32-acc on this arch)
__device__ __forceinline__ void mma16816h(uint32_t* c, const uint32_t* a, const uint32_t* b) {
    asm volatile(
        "mma.sync.aligned.m16n8k16.row.col.f16.f16.f16.f16 "
        "{%0,%1}, {%2,%3,%4,%5}, {%6,%7}, {%0,%1};"
        : "+r"(c[0]), "+r"(c[1])
        : "r"(a[0]), "r"(a[1]), "r"(a[2]), "r"(a[3]), "r"(b[0]), "r"(b[1]));
}
// 64B rows, XOR-swizzled 16B chunks: conflict-free for ldmatrix + cp.async
__device__ __forceinline__ int swz(int row, int kc) {
    return row * 64 + (((kc ^ ((row >> 1) & 3)) & 3) << 4);
}

// ===================== split-fp16 HMMA GEMM =====================
// C[M,Ntot] = (Ah+Al)[M,K] @ (Bh+Bl)^T, 3 terms (drop Al*Bl).
// Hi term (Ah*Bh) -> f32 accum; lo terms (Ah*Bl, Al*Bh) -> shared f16 accum,
// merged into f32 after the mainloop.
// BM=128, BK=32. 128 threads = 4 warps (2m x 2n); warp tile 64 x (BN/2).
// 3-stage cp.async pipeline, 2 CTAs/SM. CTA raster swizzled in 8-wide bands.
// Per-tile K: n-tile index >= 2 uses kcB (L1 head, K=2048) else kcA.
// MODE 0: raw fp32 partials to Cf + z*8192*Ntot (split-K via gridDim.z).
// MODE 1: bias+relu, hi/lo fp16 out; bias from biasA (n0<2048) else biasB.
template <int MODE, int BN>
__global__ __launch_bounds__(128, 2) void hgemm3(
    const __half* __restrict__ Ah, const __half* __restrict__ Al, int lda,
    const __half* __restrict__ Bh, const __half* __restrict__ Bl, int ldb,
    int kcA, int kcB,
    const float* __restrict__ biasA, const float* __restrict__ biasB,
    float* __restrict__ Cf, __half* __restrict__ Chh, __half* __restrict__ Chl,
    int Ntot)
{
    constexpr int BM = 128;
    constexpr int NF   = BN / 16;                 // n-frags per warp
    constexpr int ASTB = BM * 64;                 // bytes per A sub-tile (8 KB)
    constexpr int BSTB = BN * 64;                 // bytes per B sub-tile
    constexpr int STAGEB = 2 * ASTB + 2 * BSTB;

    extern __shared__ __align__(16) char smem[];
    const uint32_t sb = s2u(smem);

    const int tid = threadIdx.x, lane = tid & 31, wid = tid >> 5;
    const int wm = wid & 1, wn = wid >> 1;        // 2x2 warp grid

    // ---- CTA raster swizzle: 8-wide column bands for L2 locality ----
    int bx = blockIdx.x, by = blockIdx.y;
    if ((gridDim.x & 7) == 0) {
        int bid = by * gridDim.x + bx;
        int band = bid / (8 * gridDim.y);
        int r = bid - band * 8 * gridDim.y;
        bx = band * 8 + (r & 7);
        by = r >> 3;
    }
    const int m0 = by * BM, n0 = bx * BN;

    // split-K slice (kc divisible by gridDim.z in all our launches)
    const int kct = (bx >= 2) ? kcB : kcA;
    const int ns = gridDim.z, z = blockIdx.z;
    const int KC = kct / ns;
    const int kbeg = z * KC;
    if (MODE == 0) Cf += (size_t)z * 8192u * (size_t)Ntot;

    auto load_tile = [&](int kt, int s) {
        const int k0 = (kbeg + kt) << 5;
        const uint32_t d = sb + (uint32_t)s * STAGEB;
#pragma unroll
        for (int i = 0; i < 4; i++) {
            int c = i * 128 + tid, r = c >> 2, kc = c & 3;
            cpa16(d + swz(r, kc), Ah + (size_t)(m0 + r) * lda + k0 + kc * 8);
        }
#pragma unroll
        for (int i = 0; i < 4; i++) {
            int c = i * 128 + tid, r = c >> 2, kc = c & 3;
            cpa16(d + ASTB + swz(r, kc), Al + (size_t)(m0 + r) * lda + k0 + kc * 8);
        }
#pragma unroll
        for (int i = 0; i < BN / 32; i++) {
            int c = i * 128 + tid, r = c >> 2, kc = c & 3;
            cpa16(d + 2 * ASTB + swz(r, kc), Bh + (size_t)(n0 + r) * ldb + k0 + kc * 8);
        }
#pragma unroll
        for (int i = 0; i < BN / 32; i++) {
            int c = i * 128 + tid, r = c >> 2, kc = c & 3;
            cpa16(d + 2 * ASTB + BSTB + swz(r, kc), Bl + (size_t)(n0 + r) * ldb + k0 + kc * 8);
        }
        asm volatile("cp.async.commit_group;" ::: "memory");
    };

    float acc[4][NF][4];
    uint32_t accH[4][NF][2];
#pragma unroll
    for (int i = 0; i < 4; i++)
#pragma unroll
        for (int j = 0; j < NF; j++) {
#pragma unroll
            for (int k = 0; k < 4; k++) acc[i][j][k] = 0.f;
            accH[i][j][0] = 0u; accH[i][j][1] = 0u;
        }

    // per-thread ldmatrix row/k mapping
    const int arow = wm * 64 + (lane & 7) + ((lane & 8) ? 8 : 0);
    const int akc0 = (lane >> 4) & 1;
    const int brow = wn * (BN / 2) + (lane & 7) + ((lane & 16) ? 8 : 0);
    const int bkc0 = (lane >> 3) & 1;

    load_tile(0, 0);
    load_tile(1, 1);

    for (int kt = 0; kt < KC; kt++) {
        asm volatile("cp.async.wait_group 1;" ::: "memory");
        __syncthreads();
        if (kt + 2 < KC) load_tile(kt + 2, (kt + 2) % 3);
        else asm volatile("cp.async.commit_group;" ::: "memory");

        const uint32_t st = sb + (uint32_t)(kt % 3) * STAGEB;
#pragma unroll
        for (int ks = 0; ks < 2; ks++) {
            uint32_t Af[4][4], Bhf[NF][2], Blf[NF][2];
            const int akc = ks * 2 + akc0;
            const int bkc = ks * 2 + bkc0;
#pragma unroll
            for (int mf = 0; mf < 4; mf++)
                ldsm4(Af[mf], st + swz(arow + mf * 16, akc));
#pragma unroll
            for (int np = 0; np < NF / 2; np++)
                ldsm4(&Bhf[2 * np][0], st + 2 * ASTB + swz(brow + np * 16, bkc));
#pragma unroll
            for (int mf = 0; mf < 4; mf++)
#pragma unroll
                for (int nf = 0; nf < NF; nf++)
                    mma16816(acc[mf][nf], Af[mf], Bhf[nf]);      // Ah*Bh -> f32
#pragma unroll
            for (int np = 0; np < NF / 2; np++)
                ldsm4(&Blf[2 * np][0], st + 2 * ASTB + BSTB + swz(brow + np * 16, bkc));
#pragma unroll
            for (int mf = 0; mf < 4; mf++)
#pragma unroll
                for (int nf = 0; nf < NF; nf++)
                    mma16816h(accH[mf][nf], Af[mf], Blf[nf]);    // Ah*Bl -> f16
#pragma unroll
            for (int mf = 0; mf < 4; mf++)
                ldsm4(Af[mf], st + ASTB + swz(arow + mf * 16, akc));
#pragma unroll
            for (int mf = 0; mf < 4; mf++)
#pragma unroll
                for (int nf = 0; nf < NF; nf++)
                    mma16816h(accH[mf][nf], Af[mf], Bhf[nf]);    // Al*Bh -> f16
        }
    }

    // merge f16 lo-accumulator into f32
#pragma unroll
    for (int mf = 0; mf < 4; mf++)
#pragma unroll
        for (int nf = 0; nf < NF; nf++) {
            __half2 h0 = *reinterpret_cast<__half2*>(&accH[mf][nf][0]);
            __half2 h1 = *reinterpret_cast<__half2*>(&accH[mf][nf][1]);
            acc[mf][nf][0] += __low2float(h0);
            acc[mf][nf][1] += __high2float(h0);
            acc[mf][nf][2] += __low2float(h1);
            acc[mf][nf][3] += __high2float(h1);
        }

    // ---------------- epilogue ----------------
    const int r0 = m0 + wm * 64 + (lane >> 2);
    const int c0 = n0 + wn * (BN / 2) + ((lane & 3) << 1);
    const float* bp = (MODE == 1) ? ((n0 < 2048) ? biasA + n0 : biasB + (n0 - 2048))
                                  : nullptr;
#pragma unroll
    for (int mf = 0; mf < 4; mf++) {
#pragma unroll
        for (int nf = 0; nf < NF; nf++) {
            const int row = r0 + mf * 16, col = c0 + nf * 8;
            if (MODE == 0) {
                *reinterpret_cast<float2*>(&Cf[(size_t)row * Ntot + col]) =
                    make_float2(acc[mf][nf][0], acc[mf][nf][1]);
                *reinterpret_cast<float2*>(&Cf[(size_t)(row + 8) * Ntot + col]) =
                    make_float2(acc[mf][nf][2], acc[mf][nf][3]);
            } else {
                const float b0 = bp[col - n0], b1 = bp[col - n0 + 1];
                float v00 = fmaxf(acc[mf][nf][0] + b0, 0.f);
                float v01 = fmaxf(acc[mf][nf][1] + b1, 0.f);
                float v10 = fmaxf(acc[mf][nf][2] + b0, 0.f);
                float v11 = fmaxf(acc[mf][nf][3] + b1, 0.f);
                __half h00 = __float2half_rn(v00), h01 = __float2half_rn(v01);
                __half h10 = __float2half_rn(v10), h11 = __float2half_rn(v11);
                *reinterpret_cast<__half2*>(&Chh[(size_t)row * Ntot + col]) = __halves2half2(h00, h01);
                *reinterpret_cast<__half2*>(&Chh[(size_t)(row + 8) * Ntot + col]) = __halves2half2(h10, h11);
                __half l00 = __float2half_rn(v00 - __half2float(h00));
                __half l01 = __float2half_rn(v01 - __half2float(h01));
                __half l10 = __float2half_rn(v10 - __half2float(h10));
                __half l11 = __float2half_rn(v11 - __half2float(h11));
                *reinterpret_cast<__half2*>(&Chl[(size_t)row * Ntot + col]) = __halves2half2(l00, l01);
                *reinterpret_cast<__half2*>(&Chl[(size_t)(row + 8) * Ntot + col]) = __halves2half2(l10, l11);
            }
        }
    }
}

// ===================== conversion kernels =====================
__global__ void split_cvt(const float* __restrict__ s, __half* __restrict__ oh,
                          __half* __restrict__ ol, int n) {
    int i = blockIdx.x * 256 + threadIdx.x;
    if (i < n) {
        float v = s[i];
        __half h = __float2half_rn(v);
        oh[i] = h;
        ol[i] = __float2half_rn(v - __half2float(h));
    }
}

// src [R,C] fp32 -> dst[c * ldd + r] fp16 hi/lo  (R, C multiples of 32)
__global__ void trans_split(const float* __restrict__ src, int R, int C, int ldd,
                            __half* __restrict__ oh, __half* __restrict__ ol) {
    __shared__ float t[32][33];
    const int c0 = blockIdx.x * 32, r0 = blockIdx.y * 32;
    const int x = threadIdx.x, y = threadIdx.y;  // (32, 8)
#pragma unroll
    for (int i = 0; i < 32; i += 8)
        t[y + i][x] = src[(size_t)(r0 + y + i) * C + c0 + x];
    __syncthreads();
#pragma unroll
    for (int i = 0; i < 32; i += 8) {
        float v = t[x][y + i];
        __half h = __float2half_rn(v);
        size_t o = (size_t)(c0 + y + i) * ldd + r0 + x;
        oh[o] = h;
        ol[o] = __float2half_rn(v - __half2float(h));
    }
}

// zero rows 320..383 (cols 0..2047) of B2 hi/lo
__global__ void zero_pad(__half* a, __half* b) {
    int i = blockIdx.x * 256 + threadIdx.x;   // 64*2048 = 131072 elements
    int r = i >> 11, c = i & 2047;
    size_t o = (size_t)(320 + r) * 4096 + c;
    a[o] = __half(0.f);
    b[o] = __half(0.f);
}

// ==== fused heads: split-K reduce + bias + relu + L1 softmax/argmax + L2 ====
// One block per row (256 threads). P: 4 partials [8192,384].
__global__ __launch_bounds__(256) void heads(
    const float* __restrict__ P,
    const float* __restrict__ b2_2, const float* __restrict__ b1_2,
    const int* __restrict__ child_parent,
    float* __restrict__ outL1, float* __restrict__ outL2)
{
    constexpr size_t S = (size_t)8192 * 384;
    const int row = blockIdx.x;
    const int j = threadIdx.x;
    const int lane = j & 31, w = j >> 5;
    const size_t base = (size_t)row * 384;

    // L2 logits (fixed-order reduce: deterministic)
    float v2 = P[base + j] + P[S + base + j] + P[2 * S + base + j] + P[3 * S + base + j]
             + b2_2[j];
    v2 = fmaxf(v2, 0.f);

    __shared__ float l1v[64];
    __shared__ float red[8];
    __shared__ int sparent;

    if (j < 64) {
        const size_t b1 = base + 256 + j;
        float v1 = P[b1] + P[S + b1] + P[2 * S + b1] + P[3 * S + b1] + b1_2[j];
        l1v[j] = fmaxf(v1, 0.f);
    }
    __syncthreads();

    // warp 0: L1 softmax + argmax (first-index tie-break)
    if (w == 0) {
        float v0 = l1v[lane], v1 = l1v[lane + 32];
        float bv; int bi;
        if (v0 >= v1) { bv = v0; bi = lane; } else { bv = v1; bi = lane + 32; }
#pragma unroll
        for (int off = 16; off; off >>= 1) {
            float ov = __shfl_xor_sync(0xFFFFFFFFu, bv, off);
            int   oi = __shfl_xor_sync(0xFFFFFFFFu, bi, off);
            if (ov > bv || (ov == bv && oi < bi)) { bv = ov; bi = oi; }
        }
        float e0 = __expf(v0 - bv), e1 = __expf(v1 - bv);
        float s = e0 + e1;
#pragma unroll
        for (int off = 16; off; off >>= 1)
            s += __shfl_xor_sync(0xFFFFFFFFu, s, off);
        float inv = 1.f / s;
        outL1[(size_t)row * 64 + lane]      = e0 * inv;
        outL1[(size_t)row * 64 + 32 + lane] = e1 * inv;
        if (lane == 0) sparent = bi;
    }
    __syncthreads();

    // L2 masked softmax over 256
    const int p = sparent;
    float v = (child_parent[j] == p) ? v2 : v2 - 10000.0f;

    float m = v;
#pragma unroll
    for (int off = 16; off; off >>= 1)
        m = fmaxf(m, __shfl_xor_sync(0xFFFFFFFFu, m, off));
    if (lane == 0) red[w] = m;
    __syncthreads();
    float bm = red[0];
#pragma unroll
    for (int i = 1; i < 8; i++) bm = fmaxf(bm, red[i]);
    __syncthreads();

    float e = __expf(v - bm);
    float s = e;
#pragma unroll
    for (int off = 16; off; off >>= 1)
        s += __shfl_xor_sync(0xFFFFFFFFu, s, off);
    if (lane == 0) red[w] = s;
    __syncthreads();
    float bs = 0.f;
#pragma unroll
    for (int i = 0; i < 8; i++) bs += red[i];

    outL2[(size_t)row * 256 + j] = e / bs;
}

// ===================== launch =====================
extern "C" void kernel_launch(void* const* d_in, const int* in_sizes, int n_in,
                              void* d_out, int out_size)
{
    const float* x    = (const float*)d_in[0];
    const float* W1_1 = (const float*)d_in[1];
    const float* b1_1 = (const float*)d_in[2];
    const float* W1_2 = (const float*)d_in[3];
    const float* b1_2 = (const float*)d_in[4];
    const float* W2_1 = (const float*)d_in[5];
    const float* b2_1 = (const float*)d_in[6];
    const float* W2_2 = (const float*)d_in[7];
    const float* b2_2 = (const float*)d_in[8];
    const int* child_parent = (const int*)d_in[9];

    float* out   = (float*)d_out;
    float* outL1 = out;
    float* outL2 = out + (size_t)8192 * 64;

    __half *xh, *xl, *hh, *hl, *B1h, *B1l, *B2h, *B2l;
    float* part;
    cudaGetSymbolAddress((void**)&xh,  g_xh);
    cudaGetSymbolAddress((void**)&xl,  g_xl);
    cudaGetSymbolAddress((void**)&hh,  g_hh);
    cudaGetSymbolAddress((void**)&hl,  g_hl);
    cudaGetSymbolAddress((void**)&B1h, g_B1h);
    cudaGetSymbolAddress((void**)&B1l, g_B1l);
    cudaGetSymbolAddress((void**)&B2h, g_B2h);
    cudaGetSymbolAddress((void**)&B2l, g_B2l);
    cudaGetSymbolAddress((void**)&part, g_part);

    constexpr int SMEM128 = 3 * (2 * 128 * 64 + 2 * 128 * 64);  // 98304
    cudaFuncSetAttribute(hgemm3<1, 128>, cudaFuncAttributeMaxDynamicSharedMemorySize, SMEM128);
    cudaFuncSetAttribute(hgemm3<0, 128>, cudaFuncAttributeMaxDynamicSharedMemorySize, SMEM128);

    // 0) x -> fp16 hi/lo
    split_cvt<<<(8192 * 1024) / 256, 256>>>(x, xh, xl, 8192 * 1024);
    // 1,2) first-layer weights -> transposed fp16 hi/lo
    trans_split<<<dim3(2048 / 32, 1024 / 32), dim3(32, 8)>>>(W1_1, 1024, 2048, 1024, B1h, B1l);
    trans_split<<<dim3(2048 / 32, 1024 / 32), dim3(32, 8)>>>(W2_1, 1024, 2048, 1024,
                                                             B1h + (size_t)2048 * 1024,
                                                             B1l + (size_t)2048 * 1024);
    // 3,4) head weights -> B2 rows 0..255 (W2_2^T), rows 256..319 (W1_2^T)
    trans_split<<<dim3(256 / 32, 4096 / 32), dim3(32, 8)>>>(W2_2, 4096, 256, 4096, B2h, B2l);
    trans_split<<<dim3(64 / 32, 2048 / 32), dim3(32, 8)>>>(W1_2, 2048, 64, 4096,
                                                           B2h + (size_t)256 * 4096,
                                                           B2l + (size_t)256 * 4096);
    // 5) zero pad rows 320..383 (cols < 2048)
    zero_pad<<<(64 * 2048) / 256, 256>>>(B2h, B2l);
    // 6) stage-1 GEMM: [h1|h2] = relu(x @ [W1_1|W2_1] + [b1_1|b2_1]) -> fp16 hi/lo
    hgemm3<1, 128><<<dim3(32, 64, 1), 128, SMEM128>>>(
        xh, xl, 1024, B1h, B1l, 1024, 32, 32, b1_1, b2_1, nullptr, hh, hl, 4096);
    // 7) merged heads GEMM: [l2 | l1 | pad], per-tile K (4096 / 2048), split-K=4
    hgemm3<0, 128><<<dim3(3, 64, 4), 128, SMEM128>>>(
        hh, hl, 4096, B2h, B2l, 4096, 128, 64, nullptr, nullptr, part, nullptr, nullptr, 384);
    // 8) fused heads: reduce + bias + relu + L1 softmax/argmax + L2 masked softmax
    heads<<<8192, 256>>>(part, b2_2, b1_2, child_parent, outL1, outL2);
}

// round 10
// speedup vs baseline: 1.0499x; 1.0499x over previous
#include <cuda_runtime.h>
#include <cuda_fp16.h>
#include <cstdint>

// ===================== device scratch (allocation-free) =====================
__device__ __half g_xh[8192u * 1024u];
__device__ __half g_xl[8192u * 1024u];
__device__ __half g_hh[8192u * 4096u];   // [h1|h2] hi (fp16)
__device__ __half g_hl[8192u * 4096u];   // [h1|h2] lo (fp16)
__device__ __half g_B1h[4096u * 1024u];  // [W1_1|W2_1]^T hi  [4096,1024]
__device__ __half g_B1l[4096u * 1024u];
__device__ __half g_B2h[256u * 4096u];   // W2_2^T  [256,4096]
__device__ __half g_B2l[256u * 4096u];
__device__ __half g_BLh[64u * 2048u];    // W1_2^T  [64,2048]
__device__ __half g_BLl[64u * 2048u];
__device__ float g_part2[5u * 8192u * 256u];  // L2 split-K partials
__device__ float g_part1[4u * 8192u * 64u];   // L1 split-K partials

// ===================== PTX helpers (plain sm_80-era PTX only) ==============
__device__ __forceinline__ uint32_t s2u(const void* p) {
    uint32_t a;
    asm("{ .reg .u64 t; cvta.to.shared.u64 t, %1; cvt.u32.u64 %0, t; }" : "=r"(a) : "l"(p));
    return a;
}
__device__ __forceinline__ void cpa16(uint32_t d, const void* s) {
    asm volatile("cp.async.cg.shared.global [%0], [%1], 16;" :: "r"(d), "l"(s));
}
__device__ __forceinline__ void ldsm4(uint32_t* r, uint32_t a) {
    asm volatile("ldmatrix.sync.aligned.m8n8.x4.shared.b16 {%0,%1,%2,%3}, [%4];"
                 : "=r"(r[0]), "=r"(r[1]), "=r"(r[2]), "=r"(r[3]) : "r"(a));
}
__device__ __forceinline__ void mma16816(float* c, const uint32_t* a, const uint32_t* b) {
    asm volatile(
        "mma.sync.aligned.m16n8k16.row.col.f32.f16.f16.f32 "
        "{%0,%1,%2,%3}, {%4,%5,%6,%7}, {%8,%9}, {%0,%1,%2,%3};"
        : "+f"(c[0]), "+f"(c[1]), "+f"(c[2]), "+f"(c[3])
        : "r"(a[0]), "r"(a[1]), "r"(a[2]), "r"(a[3]), "r"(b[0]), "r"(b[1]));
}
// 64B rows, XOR-swizzled 16B chunks: conflict-free for ldmatrix + cp.async
__device__ __forceinline__ int swz(int row, int kc) {
    return row * 64 + (((kc ^ ((row >> 1) & 3)) & 3) << 4);
}

// ===================== split-fp16 HMMA GEMM =====================
// C[M,Ntot] = (Ah+Al)[M,K] @ (Bh+Bl)^T, 3 terms (drop Al*Bl), all f32 accum.
// BM=128, BK=32. 128 threads = 4 warps (2m x 2n); warp tile 64 x (BN/2).
// 3-stage cp.async pipeline, 2 CTAs/SM.
// CTA raster: when gridDim.x is a multiple of 8, remap to 8-wide column bands
// so each concurrent wave reuses a small set of A-panels and B-panels in L2.
// split-K via gridDim.z: z-th CTA handles its kt slice; MODE 0 writes raw fp32
// partials to Cf + z*8192*Ntot. MODE 1 (gridDim.z==1): bias+relu, hi/lo fp16
// out; bias chosen from biasA (n0<2048) or biasB.
template <int MODE, int BN>
__global__ __launch_bounds__(128, 2) void hgemm3(
    const __half* __restrict__ Ah, const __half* __restrict__ Al, int lda,
    const __half* __restrict__ Bh, const __half* __restrict__ Bl, int ldb,
    int kc_total,
    const float* __restrict__ biasA, const float* __restrict__ biasB,
    float* __restrict__ Cf, __half* __restrict__ Chh, __half* __restrict__ Chl,
    int Ntot)
{
    constexpr int BM = 128;
    constexpr int NF   = BN / 16;                 // n-frags per warp
    constexpr int ASTB = BM * 64;                 // bytes per A sub-tile (8 KB)
    constexpr int BSTB = BN * 64;                 // bytes per B sub-tile
    constexpr int STAGEB = 2 * ASTB + 2 * BSTB;

    extern __shared__ __align__(16) char smem[];
    const uint32_t sb = s2u(smem);

    const int tid = threadIdx.x, lane = tid & 31, wid = tid >> 5;
    const int wm = wid & 1, wn = wid >> 1;        // 2x2 warp grid

    // ---- CTA raster swizzle: 8-wide column bands for L2 locality ----
    int bx = blockIdx.x, by = blockIdx.y;
    if ((gridDim.x & 7) == 0) {
        int bid = by * gridDim.x + bx;
        int band = bid / (8 * gridDim.y);
        int r = bid - band * 8 * gridDim.y;
        bx = band * 8 + (r & 7);
        by = r >> 3;
    }
    const int m0 = by * BM, n0 = bx * BN;

    // split-K slice
    const int ns = gridDim.z, z = blockIdx.z;
    const int kbase = kc_total / ns, krem = kc_total % ns;
    const int KC   = kbase + (z < krem);
    const int kbeg = z * kbase + (z < krem ? z : krem);
    if (MODE == 0) Cf += (size_t)z * 8192u * (size_t)Ntot;

    auto load_tile = [&](int kt, int s) {
        const int k0 = (kbeg + kt) << 5;
        const uint32_t d = sb + (uint32_t)s * STAGEB;
#pragma unroll
        for (int i = 0; i < 4; i++) {
            int c = i * 128 + tid, r = c >> 2, kc = c & 3;
            cpa16(d + swz(r, kc), Ah + (size_t)(m0 + r) * lda + k0 + kc * 8);
        }
#pragma unroll
        for (int i = 0; i < 4; i++) {
            int c = i * 128 + tid, r = c >> 2, kc = c & 3;
            cpa16(d + ASTB + swz(r, kc), Al + (size_t)(m0 + r) * lda + k0 + kc * 8);
        }
#pragma unroll
        for (int i = 0; i < BN / 32; i++) {
            int c = i * 128 + tid, r = c >> 2, kc = c & 3;
            cpa16(d + 2 * ASTB + swz(r, kc), Bh + (size_t)(n0 + r) * ldb + k0 + kc * 8);
        }
#pragma unroll
        for (int i = 0; i < BN / 32; i++) {
            int c = i * 128 + tid, r = c >> 2, kc = c & 3;
            cpa16(d + 2 * ASTB + BSTB + swz(r, kc), Bl + (size_t)(n0 + r) * ldb + k0 + kc * 8);
        }
        asm volatile("cp.async.commit_group;" ::: "memory");
    };

    float acc[4][NF][4];
#pragma unroll
    for (int i = 0; i < 4; i++)
#pragma unroll
        for (int j = 0; j < NF; j++)
#pragma unroll
            for (int k = 0; k < 4; k++) acc[i][j][k] = 0.f;

    // per-thread ldmatrix row/k mapping
    const int arow = wm * 64 + (lane & 7) + ((lane & 8) ? 8 : 0);
    const int akc0 = (lane >> 4) & 1;
    const int brow = wn * (BN / 2) + (lane & 7) + ((lane & 16) ? 8 : 0);
    const int bkc0 = (lane >> 3) & 1;

    load_tile(0, 0);
    load_tile(1, 1);

    for (int kt = 0; kt < KC; kt++) {
        asm volatile("cp.async.wait_group 1;" ::: "memory");
        __syncthreads();
        if (kt + 2 < KC) load_tile(kt + 2, (kt + 2) % 3);
        else asm volatile("cp.async.commit_group;" ::: "memory");

        const uint32_t st = sb + (uint32_t)(kt % 3) * STAGEB;
#pragma unroll
        for (int ks = 0; ks < 2; ks++) {
            uint32_t Af[4][4], Bhf[NF][2], Blf[NF][2];
            const int akc = ks * 2 + akc0;
            const int bkc = ks * 2 + bkc0;
#pragma unroll
            for (int mf = 0; mf < 4; mf++)
                ldsm4(Af[mf], st + swz(arow + mf * 16, akc));
#pragma unroll
            for (int np = 0; np < NF / 2; np++)
                ldsm4(&Bhf[2 * np][0], st + 2 * ASTB + swz(brow + np * 16, bkc));
#pragma unroll
            for (int mf = 0; mf < 4; mf++)
#pragma unroll
                for (int nf = 0; nf < NF; nf++)
                    mma16816(acc[mf][nf], Af[mf], Bhf[nf]);     // Ah * Bh
#pragma unroll
            for (int np = 0; np < NF / 2; np++)
                ldsm4(&Blf[2 * np][0], st + 2 * ASTB + BSTB + swz(brow + np * 16, bkc));
#pragma unroll
            for (int mf = 0; mf < 4; mf++)
#pragma unroll
                for (int nf = 0; nf < NF; nf++)
                    mma16816(acc[mf][nf], Af[mf], Blf[nf]);     // Ah * Bl
#pragma unroll
            for (int mf = 0; mf < 4; mf++)
                ldsm4(Af[mf], st + ASTB + swz(arow + mf * 16, akc));
#pragma unroll
            for (int mf = 0; mf < 4; mf++)
#pragma unroll
                for (int nf = 0; nf < NF; nf++)
                    mma16816(acc[mf][nf], Af[mf], Bhf[nf]);     // Al * Bh
        }
    }

    // ---------------- epilogue ----------------
    const int r0 = m0 + wm * 64 + (lane >> 2);
    const int c0 = n0 + wn * (BN / 2) + ((lane & 3) << 1);
    const float* bp = (MODE == 1) ? ((n0 < 2048) ? biasA + n0 : biasB + (n0 - 2048))
                                  : nullptr;
#pragma unroll
    for (int mf = 0; mf < 4; mf++) {
#pragma unroll
        for (int nf = 0; nf < NF; nf++) {
            const int row = r0 + mf * 16, col = c0 + nf * 8;
            if (MODE == 0) {
                *reinterpret_cast<float2*>(&Cf[(size_t)row * Ntot + col]) =
                    make_float2(acc[mf][nf][0], acc[mf][nf][1]);
                *reinterpret_cast<float2*>(&Cf[(size_t)(row + 8) * Ntot + col]) =
                    make_float2(acc[mf][nf][2], acc[mf][nf][3]);
            } else {
                const float b0 = bp[col - n0], b1 = bp[col - n0 + 1];
                float v00 = fmaxf(acc[mf][nf][0] + b0, 0.f);
                float v01 = fmaxf(acc[mf][nf][1] + b1, 0.f);
                float v10 = fmaxf(acc[mf][nf][2] + b0, 0.f);
                float v11 = fmaxf(acc[mf][nf][3] + b1, 0.f);
                __half h00 = __float2half_rn(v00), h01 = __float2half_rn(v01);
                __half h10 = __float2half_rn(v10), h11 = __float2half_rn(v11);
                *reinterpret_cast<__half2*>(&Chh[(size_t)row * Ntot + col]) = __halves2half2(h00, h01);
                *reinterpret_cast<__half2*>(&Chh[(size_t)(row + 8) * Ntot + col]) = __halves2half2(h10, h11);
                __half l00 = __float2half_rn(v00 - __half2float(h00));
                __half l01 = __float2half_rn(v01 - __half2float(h01));
                __half l10 = __float2half_rn(v10 - __half2float(h10));
                __half l11 = __float2half_rn(v11 - __half2float(h11));
                *reinterpret_cast<__half2*>(&Chl[(size_t)row * Ntot + col]) = __halves2half2(l00, l01);
                *reinterpret_cast<__half2*>(&Chl[(size_t)(row + 8) * Ntot + col]) = __halves2half2(l10, l11);
            }
        }
    }
}

// ===================== conversion kernels =====================
__global__ void split_cvt(const float* __restrict__ s, __half* __restrict__ oh,
                          __half* __restrict__ ol, int n) {
    int i = blockIdx.x * 256 + threadIdx.x;
    if (i < n) {
        float v = s[i];
        __half h = __float2half_rn(v);
        oh[i] = h;
        ol[i] = __float2half_rn(v - __half2float(h));
    }
}

// src [R,C] fp32 -> dst[c * ldd + r] fp16 hi/lo  (R, C multiples of 32)
__global__ void trans_split(const float* __restrict__ src, int R, int C, int ldd,
                            __half* __restrict__ oh, __half* __restrict__ ol) {
    __shared__ float t[32][33];
    const int c0 = blockIdx.x * 32, r0 = blockIdx.y * 32;
    const int x = threadIdx.x, y = threadIdx.y;  // (32, 8)
#pragma unroll
    for (int i = 0; i < 32; i += 8)
        t[y + i][x] = src[(size_t)(r0 + y + i) * C + c0 + x];
    __syncthreads();
#pragma unroll
    for (int i = 0; i < 32; i += 8) {
        float v = t[x][y + i];
        __half h = __float2half_rn(v);
        size_t o = (size_t)(c0 + y + i) * ldd + r0 + x;
        oh[o] = h;
        ol[o] = __float2half_rn(v - __half2float(h));
    }
}

// ==== fused heads: split-K reduce + bias + relu + L1 softmax/argmax + L2 ====
// One block per row (256 threads). P2: 5 partials [8192,256]; P1: 4 partials [8192,64].
__global__ __launch_bounds__(256) void heads(
    const float* __restrict__ P2, const float* __restrict__ P1,
    const float* __restrict__ b2_2, const float* __restrict__ b1_2,
    const int* __restrict__ child_parent,
    float* __restrict__ outL1, float* __restrict__ outL2)
{
    constexpr size_t S2 = (size_t)8192 * 256;
    constexpr size_t S1 = (size_t)8192 * 64;
    const int row = blockIdx.x;
    const int j = threadIdx.x;
    const int lane = j & 31, w = j >> 5;

    // L2 logits (fixed-order reduce: deterministic)
    const size_t b2 = (size_t)row * 256 + j;
    float v2 = P2[b2] + P2[S2 + b2] + P2[2 * S2 + b2] + P2[3 * S2 + b2] + P2[4 * S2 + b2]
             + b2_2[j];
    v2 = fmaxf(v2, 0.f);

    __shared__ float l1v[64];
    __shared__ float red[8];
    __shared__ int sparent;

    if (j < 64) {
        const size_t b1 = (size_t)row * 64 + j;
        float v1 = P1[b1] + P1[S1 + b1] + P1[2 * S1 + b1] + P1[3 * S1 + b1] + b1_2[j];
        l1v[j] = fmaxf(v1, 0.f);
    }
    __syncthreads();

    // warp 0: L1 softmax + argmax (first-index tie-break)
    if (w == 0) {
        float v0 = l1v[lane], v1 = l1v[lane + 32];
        float bv; int bi;
        if (v0 >= v1) { bv = v0; bi = lane; } else { bv = v1; bi = lane + 32; }
#pragma unroll
        for (int off = 16; off; off >>= 1) {
            float ov = __shfl_xor_sync(0xFFFFFFFFu, bv, off);
            int   oi = __shfl_xor_sync(0xFFFFFFFFu, bi, off);
            if (ov > bv || (ov == bv && oi < bi)) { bv = ov; bi = oi; }
        }
        float e0 = __expf(v0 - bv), e1 = __expf(v1 - bv);
        float s = e0 + e1;
#pragma unroll
        for (int off = 16; off; off >>= 1)
            s += __shfl_xor_sync(0xFFFFFFFFu, s, off);
        float inv = 1.f / s;
        outL1[(size_t)row * 64 + lane]      = e0 * inv;
        outL1[(size_t)row * 64 + 32 + lane] = e1 * inv;
        if (lane == 0) sparent = bi;
    }
    __syncthreads();

    // L2 masked softmax over 256
    const int p = sparent;
    float v = (child_parent[j] == p) ? v2 : v2 - 10000.0f;

    float m = v;
#pragma unroll
    for (int off = 16; off; off >>= 1)
        m = fmaxf(m, __shfl_xor_sync(0xFFFFFFFFu, m, off));
    if (lane == 0) red[w] = m;
    __syncthreads();
    float bm = red[0];
#pragma unroll
    for (int i = 1; i < 8; i++) bm = fmaxf(bm, red[i]);
    __syncthreads();

    float e = __expf(v - bm);
    float s = e;
#pragma unroll
    for (int off = 16; off; off >>= 1)
        s += __shfl_xor_sync(0xFFFFFFFFu, s, off);
    if (lane == 0) red[w] = s;
    __syncthreads();
    float bs = 0.f;
#pragma unroll
    for (int i = 0; i < 8; i++) bs += red[i];

    outL2[(size_t)row * 256 + j] = e / bs;
}

// ===================== launch =====================
extern "C" void kernel_launch(void* const* d_in, const int* in_sizes, int n_in,
                              void* d_out, int out_size)
{
    const float* x    = (const float*)d_in[0];
    const float* W1_1 = (const float*)d_in[1];
    const float* b1_1 = (const float*)d_in[2];
    const float* W1_2 = (const float*)d_in[3];
    const float* b1_2 = (const float*)d_in[4];
    const float* W2_1 = (const float*)d_in[5];
    const float* b2_1 = (const float*)d_in[6];
    const float* W2_2 = (const float*)d_in[7];
    const float* b2_2 = (const float*)d_in[8];
    const int* child_parent = (const int*)d_in[9];

    float* out   = (float*)d_out;
    float* outL1 = out;
    float* outL2 = out + (size_t)8192 * 64;

    __half *xh, *xl, *hh, *hl, *B1h, *B1l, *B2h, *B2l, *BLh, *BLl;
    float *part2, *part1;
    cudaGetSymbolAddress((void**)&xh,  g_xh);
    cudaGetSymbolAddress((void**)&xl,  g_xl);
    cudaGetSymbolAddress((void**)&hh,  g_hh);
    cudaGetSymbolAddress((void**)&hl,  g_hl);
    cudaGetSymbolAddress((void**)&B1h, g_B1h);
    cudaGetSymbolAddress((void**)&B1l, g_B1l);
    cudaGetSymbolAddress((void**)&B2h, g_B2h);
    cudaGetSymbolAddress((void**)&B2l, g_B2l);
    cudaGetSymbolAddress((void**)&BLh, g_BLh);
    cudaGetSymbolAddress((void**)&BLl, g_BLl);
    cudaGetSymbolAddress((void**)&part2, g_part2);
    cudaGetSymbolAddress((void**)&part1, g_part1);

    constexpr int SMEM128 = 3 * (2 * 128 * 64 + 2 * 128 * 64);  // 98304
    constexpr int SMEM64  = 3 * (2 * 128 * 64 + 2 * 64 * 64);   // 73728
    cudaFuncSetAttribute(hgemm3<1, 128>, cudaFuncAttributeMaxDynamicSharedMemorySize, SMEM128);
    cudaFuncSetAttribute(hgemm3<0, 128>, cudaFuncAttributeMaxDynamicSharedMemorySize, SMEM128);
    cudaFuncSetAttribute(hgemm3<0, 64>,  cudaFuncAttributeMaxDynamicSharedMemorySize, SMEM64);

    // 0) x -> fp16 hi/lo
    split_cvt<<<(8192 * 1024) / 256, 256>>>(x, xh, xl, 8192 * 1024);
    // 1,2) first-layer weights -> transposed fp16 hi/lo
    trans_split<<<dim3(2048 / 32, 1024 / 32), dim3(32, 8)>>>(W1_1, 1024, 2048, 1024, B1h, B1l);
    trans_split<<<dim3(2048 / 32, 1024 / 32), dim3(32, 8)>>>(W2_1, 1024, 2048, 1024,
                                                             B1h + (size_t)2048 * 1024,
                                                             B1l + (size_t)2048 * 1024);
    // 3,4) head weights -> transposed fp16 hi/lo
    trans_split<<<dim3(256 / 32, 4096 / 32), dim3(32, 8)>>>(W2_2, 4096, 256, 4096, B2h, B2l);
    trans_split<<<dim3(64 / 32, 2048 / 32), dim3(32, 8)>>>(W1_2, 2048, 64, 2048, BLh, BLl);
    // 5) stage-1 GEMM: [h1|h2] = relu(x @ [W1_1|W2_1] + [b1_1|b2_1]) -> fp16 hi/lo
    hgemm3<1, 128><<<dim3(32, 64, 1), 128, SMEM128>>>(
        xh, xl, 1024, B1h, B1l, 1024, 32, b1_1, b2_1, nullptr, hh, hl, 4096);
    // 6) L2 logits GEMM, split-K=5 -> raw fp32 partials  (N=256, K=4096)
    hgemm3<0, 128><<<dim3(2, 64, 5), 128, SMEM128>>>(
        hh, hl, 4096, B2h, B2l, 4096, 128, nullptr, nullptr, part2, nullptr, nullptr, 256);
    // 7) L1 head GEMM, split-K=4 -> raw fp32 partials  (N=64, K=2048, h1 only)
    hgemm3<0, 64><<<dim3(1, 64, 4), 128, SMEM64>>>(
        hh, hl, 4096, BLh, BLl, 2048, 64, nullptr, nullptr, part1, nullptr, nullptr, 64);
    // 8) fused heads: reduce + bias + relu + L1 softmax/argmax + L2 masked softmax
    heads<<<8192, 256>>>(part2, part1, b2_2, b1_2, child_parent, outL1, outL2);
}

// round 11
// speedup vs baseline: 1.0825x; 1.0311x over previous
#include <cuda_runtime.h>
#include <cuda_fp16.h>
#include <cstdint>

// ===================== device scratch (allocation-free) =====================
__device__ __half g_xh[8192u * 1024u];
__device__ __half g_xl[8192u * 1024u];
__device__ __half g_hh[8192u * 4096u];   // [h1|h2] hi (fp16)
__device__ __half g_hl[8192u * 4096u];   // [h1|h2] lo (fp16)
__device__ __half g_B1h[4096u * 1024u];  // [W1_1|W2_1]^T hi  [4096,1024]
__device__ __half g_B1l[4096u * 1024u];
__device__ __half g_B2h[256u * 4096u];   // W2_2^T  [256,4096]
__device__ __half g_B2l[256u * 4096u];
__device__ __half g_BLh[64u * 2048u];    // W1_2^T  [64,2048]
__device__ __half g_BLl[64u * 2048u];
__device__ float g_part2[5u * 8192u * 256u];  // L2 split-K partials
__device__ float g_part1[4u * 8192u * 64u];   // L1 split-K partials

// ===================== PTX helpers (plain sm_80-era PTX only) ==============
__device__ __forceinline__ uint32_t s2u(const void* p) {
    uint32_t a;
    asm("{ .reg .u64 t; cvta.to.shared.u64 t, %1; cvt.u32.u64 %0, t; }" : "=r"(a) : "l"(p));
    return a;
}
__device__ __forceinline__ void cpa16(uint32_t d, const void* s) {
    asm volatile("cp.async.cg.shared.global [%0], [%1], 16;" :: "r"(d), "l"(s));
}
__device__ __forceinline__ void ldsm4(uint32_t* r, uint32_t a) {
    asm volatile("ldmatrix.sync.aligned.m8n8.x4.shared.b16 {%0,%1,%2,%3}, [%4];"
                 : "=r"(r[0]), "=r"(r[1]), "=r"(r[2]), "=r"(r[3]) : "r"(a));
}
__device__ __forceinline__ void mma16816(float* c, const uint32_t* a, const uint32_t* b) {
    asm volatile(
        "mma.sync.aligned.m16n8k16.row.col.f32.f16.f16.f32 "
        "{%0,%1,%2,%3}, {%4,%5,%6,%7}, {%8,%9}, {%0,%1,%2,%3};"
        : "+f"(c[0]), "+f"(c[1]), "+f"(c[2]), "+f"(c[3])
        : "r"(a[0]), "r"(a[1]), "r"(a[2]), "r"(a[3]), "r"(b[0]), "r"(b[1]));
}
// 64B rows, XOR-swizzled 16B chunks: conflict-free for ldmatrix + cp.async
__device__ __forceinline__ int swz(int row, int kc) {
    return row * 64 + (((kc ^ ((row >> 1) & 3)) & 3) << 4);
}

// ===================== split-fp16 HMMA GEMM =====================
// C[M,Ntot] = (Ah+Al)[M,K] @ (Bh+Bl)^T, 3 terms (drop Al*Bl), all f32 accum.
// BM=128, BK=32. 128 threads = 4 warps (2m x 2n); warp tile 64 x (BN/2).
// 3-stage cp.async pipeline, 2 CTAs/SM.
// split-K via gridDim.z: z-th CTA handles its kt slice; MODE 0 writes raw fp32
// partials to Cf + z*8192*Ntot. MODE 1 (gridDim.z==1): bias+relu, hi/lo fp16
// out; bias chosen from biasA (n0<2048) or biasB.
template <int MODE, int BN>
__global__ __launch_bounds__(128, 2) void hgemm3(
    const __half* __restrict__ Ah, const __half* __restrict__ Al, int lda,
    const __half* __restrict__ Bh, const __half* __restrict__ Bl, int ldb,
    int kc_total,
    const float* __restrict__ biasA, const float* __restrict__ biasB,
    float* __restrict__ Cf, __half* __restrict__ Chh, __half* __restrict__ Chl,
    int Ntot)
{
    constexpr int BM = 128;
    constexpr int NF   = BN / 16;                 // n-frags per warp
    constexpr int ASTB = BM * 64;                 // bytes per A sub-tile (8 KB)
    constexpr int BSTB = BN * 64;                 // bytes per B sub-tile
    constexpr int STAGEB = 2 * ASTB + 2 * BSTB;

    extern __shared__ __align__(16) char smem[];
    const uint32_t sb = s2u(smem);

    const int tid = threadIdx.x, lane = tid & 31, wid = tid >> 5;
    const int wm = wid & 1, wn = wid >> 1;        // 2x2 warp grid
    const int m0 = blockIdx.y * BM, n0 = blockIdx.x * BN;

    // split-K slice
    const int ns = gridDim.z, z = blockIdx.z;
    const int kbase = kc_total / ns, krem = kc_total % ns;
    const int KC   = kbase + (z < krem);
    const int kbeg = z * kbase + (z < krem ? z : krem);
    if (MODE == 0) Cf += (size_t)z * 8192u * (size_t)Ntot;

    auto load_tile = [&](int kt, int s) {
        const int k0 = (kbeg + kt) << 5;
        const uint32_t d = sb + (uint32_t)s * STAGEB;
#pragma unroll
        for (int i = 0; i < 4; i++) {
            int c = i * 128 + tid, r = c >> 2, kc = c & 3;
            cpa16(d + swz(r, kc), Ah + (size_t)(m0 + r) * lda + k0 + kc * 8);
        }
#pragma unroll
        for (int i = 0; i < 4; i++) {
            int c = i * 128 + tid, r = c >> 2, kc = c & 3;
            cpa16(d + ASTB + swz(r, kc), Al + (size_t)(m0 + r) * lda + k0 + kc * 8);
        }
#pragma unroll
        for (int i = 0; i < BN / 32; i++) {
            int c = i * 128 + tid, r = c >> 2, kc = c & 3;
            cpa16(d + 2 * ASTB + swz(r, kc), Bh + (size_t)(n0 + r) * ldb + k0 + kc * 8);
        }
#pragma unroll
        for (int i = 0; i < BN / 32; i++) {
            int c = i * 128 + tid, r = c >> 2, kc = c & 3;
            cpa16(d + 2 * ASTB + BSTB + swz(r, kc), Bl + (size_t)(n0 + r) * ldb + k0 + kc * 8);
        }
        asm volatile("cp.async.commit_group;" ::: "memory");
    };

    float acc[4][NF][4];
#pragma unroll
    for (int i = 0; i < 4; i++)
#pragma unroll
        for (int j = 0; j < NF; j++)
#pragma unroll
            for (int k = 0; k < 4; k++) acc[i][j][k] = 0.f;

    // per-thread ldmatrix row/k mapping
    const int arow = wm * 64 + (lane & 7) + ((lane & 8) ? 8 : 0);
    const int akc0 = (lane >> 4) & 1;
    const int brow = wn * (BN / 2) + (lane & 7) + ((lane & 16) ? 8 : 0);
    const int bkc0 = (lane >> 3) & 1;

    load_tile(0, 0);
    load_tile(1, 1);

    for (int kt = 0; kt < KC; kt++) {
        asm volatile("cp.async.wait_group 1;" ::: "memory");
        __syncthreads();
        if (kt + 2 < KC) load_tile(kt + 2, (kt + 2) % 3);
        else asm volatile("cp.async.commit_group;" ::: "memory");

        const uint32_t st = sb + (uint32_t)(kt % 3) * STAGEB;
#pragma unroll
        for (int ks = 0; ks < 2; ks++) {
            uint32_t Af[4][4], Bhf[NF][2], Blf[NF][2];
            const int akc = ks * 2 + akc0;
            const int bkc = ks * 2 + bkc0;
#pragma unroll
            for (int mf = 0; mf < 4; mf++)
                ldsm4(Af[mf], st + swz(arow + mf * 16, akc));
#pragma unroll
            for (int np = 0; np < NF / 2; np++)
                ldsm4(&Bhf[2 * np][0], st + 2 * ASTB + swz(brow + np * 16, bkc));
#pragma unroll
            for (int mf = 0; mf < 4; mf++)
#pragma unroll
                for (int nf = 0; nf < NF; nf++)
                    mma16816(acc[mf][nf], Af[mf], Bhf[nf]);     // Ah * Bh
#pragma unroll
            for (int np = 0; np < NF / 2; np++)
                ldsm4(&Blf[2 * np][0], st + 2 * ASTB + BSTB + swz(brow + np * 16, bkc));
#pragma unroll
            for (int mf = 0; mf < 4; mf++)
#pragma unroll
                for (int nf = 0; nf < NF; nf++)
                    mma16816(acc[mf][nf], Af[mf], Blf[nf]);     // Ah * Bl
#pragma unroll
            for (int mf = 0; mf < 4; mf++)
                ldsm4(Af[mf], st + ASTB + swz(arow + mf * 16, akc));
#pragma unroll
            for (int mf = 0; mf < 4; mf++)
#pragma unroll
                for (int nf = 0; nf < NF; nf++)
                    mma16816(acc[mf][nf], Af[mf], Bhf[nf]);     // Al * Bh
        }
    }

    // ---------------- epilogue ----------------
    const int r0 = m0 + wm * 64 + (lane >> 2);
    const int c0 = n0 + wn * (BN / 2) + ((lane & 3) << 1);
    const float* bp = (MODE == 1) ? ((n0 < 2048) ? biasA + n0 : biasB + (n0 - 2048))
                                  : nullptr;
#pragma unroll
    for (int mf = 0; mf < 4; mf++) {
#pragma unroll
        for (int nf = 0; nf < NF; nf++) {
            const int row = r0 + mf * 16, col = c0 + nf * 8;
            if (MODE == 0) {
                *reinterpret_cast<float2*>(&Cf[(size_t)row * Ntot + col]) =
                    make_float2(acc[mf][nf][0], acc[mf][nf][1]);
                *reinterpret_cast<float2*>(&Cf[(size_t)(row + 8) * Ntot + col]) =
                    make_float2(acc[mf][nf][2], acc[mf][nf][3]);
            } else {
                const float b0 = bp[col - n0], b1 = bp[col - n0 + 1];
                float v00 = fmaxf(acc[mf][nf][0] + b0, 0.f);
                float v01 = fmaxf(acc[mf][nf][1] + b1, 0.f);
                float v10 = fmaxf(acc[mf][nf][2] + b0, 0.f);
                float v11 = fmaxf(acc[mf][nf][3] + b1, 0.f);
                __half h00 = __float2half_rn(v00), h01 = __float2half_rn(v01);
                __half h10 = __float2half_rn(v10), h11 = __float2half_rn(v11);
                *reinterpret_cast<__half2*>(&Chh[(size_t)row * Ntot + col]) = __halves2half2(h00, h01);
                *reinterpret_cast<__half2*>(&Chh[(size_t)(row + 8) * Ntot + col]) = __halves2half2(h10, h11);
                __half l00 = __float2half_rn(v00 - __half2float(h00));
                __half l01 = __float2half_rn(v01 - __half2float(h01));
                __half l10 = __float2half_rn(v10 - __half2float(h10));
                __half l11 = __float2half_rn(v11 - __half2float(h11));
                *reinterpret_cast<__half2*>(&Chl[(size_t)row * Ntot + col]) = __halves2half2(l00, l01);
                *reinterpret_cast<__half2*>(&Chl[(size_t)(row + 8) * Ntot + col]) = __halves2half2(l10, l11);
            }
        }
    }
}

// ===================== conversion kernels =====================
// vectorized: 4 fp32 -> 4 hi fp16 + 4 lo fp16 per thread
__global__ void split_cvt4(const float4* __restrict__ s, __half2* __restrict__ oh,
                           __half2* __restrict__ ol, int n4) {
    int i = blockIdx.x * 256 + threadIdx.x;
    if (i < n4) {
        float4 v = s[i];
        __half h0 = __float2half_rn(v.x), h1 = __float2half_rn(v.y);
        __half h2 = __float2half_rn(v.z), h3 = __float2half_rn(v.w);
        oh[2 * i]     = __halves2half2(h0, h1);
        oh[2 * i + 1] = __halves2half2(h2, h3);
        __half l0 = __float2half_rn(v.x - __half2float(h0));
        __half l1 = __float2half_rn(v.y - __half2float(h1));
        __half l2 = __float2half_rn(v.z - __half2float(h2));
        __half l3 = __float2half_rn(v.w - __half2float(h3));
        ol[2 * i]     = __halves2half2(l0, l1);
        ol[2 * i + 1] = __halves2half2(l2, l3);
    }
}

// transpose+split one 32x32 tile: src [R,C] fp32 -> dst[c * ldd + r] fp16 hi/lo
__device__ __forceinline__ void trans_tile(
    const float* __restrict__ src, int C, int ldd, int r0, int c0,
    __half* __restrict__ oh, __half* __restrict__ ol,
    int x, int y)
{
    __shared__ float t[32][33];
#pragma unroll
    for (int i = 0; i < 32; i += 8)
        t[y + i][x] = src[(size_t)(r0 + y + i) * C + c0 + x];
    __syncthreads();
#pragma unroll
    for (int i = 0; i < 32; i += 8) {
        float v = t[x][y + i];
        __half h = __float2half_rn(v);
        size_t o = (size_t)(c0 + y + i) * ldd + r0 + x;
        oh[o] = h;
        ol[o] = __float2half_rn(v - __half2float(h));
    }
}

__global__ void trans_split(const float* __restrict__ src, int R, int C, int ldd,
                            __half* __restrict__ oh, __half* __restrict__ ol) {
    trans_tile(src, C, ldd, blockIdx.y * 32, blockIdx.x * 32, oh, ol,
               threadIdx.x, threadIdx.y);
}

// merged head-weight transposes: W2_2 [4096,256]->B2 [256,4096] (1024 tiles),
// then W1_2 [2048,64]->BL [64,2048] (128 tiles). flat grid of 1152 blocks.
__global__ void trans_heads(const float* __restrict__ W2_2, __half* __restrict__ B2h,
                            __half* __restrict__ B2l,
                            const float* __restrict__ W1_2, __half* __restrict__ BLh,
                            __half* __restrict__ BLl) {
    int b = blockIdx.x;
    if (b < 1024) {
        int bx = b & 7, by = b >> 3;         // 8 col-tiles x 128 row-tiles
        trans_tile(W2_2, 256, 4096, by * 32, bx * 32, B2h, B2l,
                   threadIdx.x, threadIdx.y);
    } else {
        b -= 1024;
        int bx = b & 1, by = b >> 1;         // 2 col-tiles x 64 row-tiles
        trans_tile(W1_2, 64, 2048, by * 32, bx * 32, BLh, BLl,
                   threadIdx.x, threadIdx.y);
    }
}

// ==== fused heads: split-K reduce + bias + relu + L1 softmax/argmax + L2 ====
// One block per row (256 threads). P2: 5 partials [8192,256]; P1: 4 partials [8192,64].
__global__ __launch_bounds__(256) void heads(
    const float* __restrict__ P2, const float* __restrict__ P1,
    const float* __restrict__ b2_2, const float* __restrict__ b1_2,
    const int* __restrict__ child_parent,
    float* __restrict__ outL1, float* __restrict__ outL2)
{
    constexpr size_t S2 = (size_t)8192 * 256;
    constexpr size_t S1 = (size_t)8192 * 64;
    const int row = blockIdx.x;
    const int j = threadIdx.x;
    const int lane = j & 31, w = j >> 5;

    // L2 logits (fixed-order reduce: deterministic)
    const size_t b2 = (size_t)row * 256 + j;
    float v2 = P2[b2] + P2[S2 + b2] + P2[2 * S2 + b2] + P2[3 * S2 + b2] + P2[4 * S2 + b2]
             + b2_2[j];
    v2 = fmaxf(v2, 0.f);

    __shared__ float l1v[64];
    __shared__ float red[8];
    __shared__ int sparent;

    if (j < 64) {
        const size_t b1 = (size_t)row * 64 + j;
        float v1 = P1[b1] + P1[S1 + b1] + P1[2 * S1 + b1] + P1[3 * S1 + b1] + b1_2[j];
        l1v[j] = fmaxf(v1, 0.f);
    }
    __syncthreads();

    // warp 0: L1 softmax + argmax (first-index tie-break)
    if (w == 0) {
        float v0 = l1v[lane], v1 = l1v[lane + 32];
        float bv; int bi;
        if (v0 >= v1) { bv = v0; bi = lane; } else { bv = v1; bi = lane + 32; }
#pragma unroll
        for (int off = 16; off; off >>= 1) {
            float ov = __shfl_xor_sync(0xFFFFFFFFu, bv, off);
            int   oi = __shfl_xor_sync(0xFFFFFFFFu, bi, off);
            if (ov > bv || (ov == bv && oi < bi)) { bv = ov; bi = oi; }
        }
        float e0 = __expf(v0 - bv), e1 = __expf(v1 - bv);
        float s = e0 + e1;
#pragma unroll
        for (int off = 16; off; off >>= 1)
            s += __shfl_xor_sync(0xFFFFFFFFu, s, off);
        float inv = 1.f / s;
        outL1[(size_t)row * 64 + lane]      = e0 * inv;
        outL1[(size_t)row * 64 + 32 + lane] = e1 * inv;
        if (lane == 0) sparent = bi;
    }
    __syncthreads();

    // L2 masked softmax over 256
    const int p = sparent;
    float v = (child_parent[j] == p) ? v2 : v2 - 10000.0f;

    float m = v;
#pragma unroll
    for (int off = 16; off; off >>= 1)
        m = fmaxf(m, __shfl_xor_sync(0xFFFFFFFFu, m, off));
    if (lane == 0) red[w] = m;
    __syncthreads();
    float bm = red[0];
#pragma unroll
    for (int i = 1; i < 8; i++) bm = fmaxf(bm, red[i]);
    __syncthreads();

    float e = __expf(v - bm);
    float s = e;
#pragma unroll
    for (int off = 16; off; off >>= 1)
        s += __shfl_xor_sync(0xFFFFFFFFu, s, off);
    if (lane == 0) red[w] = s;
    __syncthreads();
    float bs = 0.f;
#pragma unroll
    for (int i = 0; i < 8; i++) bs += red[i];

    outL2[(size_t)row * 256 + j] = e / bs;
}

// ===================== launch =====================
extern "C" void kernel_launch(void* const* d_in, const int* in_sizes, int n_in,
                              void* d_out, int out_size)
{
    const float* x    = (const float*)d_in[0];
    const float* W1_1 = (const float*)d_in[1];
    const float* b1_1 = (const float*)d_in[2];
    const float* W1_2 = (const float*)d_in[3];
    const float* b1_2 = (const float*)d_in[4];
    const float* W2_1 = (const float*)d_in[5];
    const float* b2_1 = (const float*)d_in[6];
    const float* W2_2 = (const float*)d_in[7];
    const float* b2_2 = (const float*)d_in[8];
    const int* child_parent = (const int*)d_in[9];

    float* out   = (float*)d_out;
    float* outL1 = out;
    float* outL2 = out + (size_t)8192 * 64;

    __half *xh, *xl, *hh, *hl, *B1h, *B1l, *B2h, *B2l, *BLh, *BLl;
    float *part2, *part1;
    cudaGetSymbolAddress((void**)&xh,  g_xh);
    cudaGetSymbolAddress((void**)&xl,  g_xl);
    cudaGetSymbolAddress((void**)&hh,  g_hh);
    cudaGetSymbolAddress((void**)&hl,  g_hl);
    cudaGetSymbolAddress((void**)&B1h, g_B1h);
    cudaGetSymbolAddress((void**)&B1l, g_B1l);
    cudaGetSymbolAddress((void**)&B2h, g_B2h);
    cudaGetSymbolAddress((void**)&B2l, g_B2l);
    cudaGetSymbolAddress((void**)&BLh, g_BLh);
    cudaGetSymbolAddress((void**)&BLl, g_BLl);
    cudaGetSymbolAddress((void**)&part2, g_part2);
    cudaGetSymbolAddress((void**)&part1, g_part1);

    constexpr int SMEM128 = 3 * (2 * 128 * 64 + 2 * 128 * 64);  // 98304
    constexpr int SMEM64  = 3 * (2 * 128 * 64 + 2 * 64 * 64);   // 73728
    cudaFuncSetAttribute(hgemm3<1, 128>, cudaFuncAttributeMaxDynamicSharedMemorySize, SMEM128);
    cudaFuncSetAttribute(hgemm3<0, 128>, cudaFuncAttributeMaxDynamicSharedMemorySize, SMEM128);
    cudaFuncSetAttribute(hgemm3<0, 64>,  cudaFuncAttributeMaxDynamicSharedMemorySize, SMEM64);

    // 0) x -> fp16 hi/lo (vectorized)
    split_cvt4<<<(8192 * 1024 / 4) / 256, 256>>>(
        (const float4*)x, (__half2*)xh, (__half2*)xl, 8192 * 1024 / 4);
    // 1,2) first-layer weights -> transposed fp16 hi/lo
    trans_split<<<dim3(2048 / 32, 1024 / 32), dim3(32, 8)>>>(W1_1, 1024, 2048, 1024, B1h, B1l);
    trans_split<<<dim3(2048 / 32, 1024 / 32), dim3(32, 8)>>>(W2_1, 1024, 2048, 1024,
                                                             B1h + (size_t)2048 * 1024,
                                                             B1l + (size_t)2048 * 1024);
    // 3) stage-1 GEMM (launch index 3 -> lands in ncu's captured slot)
    hgemm3<1, 128><<<dim3(32, 64, 1), 128, SMEM128>>>(
        xh, xl, 1024, B1h, B1l, 1024, 32, b1_1, b2_1, nullptr, hh, hl, 4096);
    // 4) merged head-weight transposes (independent of gemm1; single launch)
    trans_heads<<<1152, dim3(32, 8)>>>(W2_2, B2h, B2l, W1_2, BLh, BLl);
    // 5) L2 logits GEMM, split-K=5 -> raw fp32 partials  (N=256, K=4096)
    hgemm3<0, 128><<<dim3(2, 64, 5), 128, SMEM128>>>(
        hh, hl, 4096, B2h, B2l, 4096, 128, nullptr, nullptr, part2, nullptr, nullptr, 256);
    // 6) L1 head GEMM, split-K=4 -> raw fp32 partials  (N=64, K=2048, h1 only)
    hgemm3<0, 64><<<dim3(1, 64, 4), 128, SMEM64>>>(
        hh, hl, 4096, BLh, BLl, 2048, 64, nullptr, nullptr, part1, nullptr, nullptr, 64);
    // 7) fused heads: reduce + bias + relu + L1 softmax/argmax + L2 masked softmax
    heads<<<8192, 256>>>(part2, part1, b2_2, b1_2, child_parent, outL1, outL2);
}

// round 12
// speedup vs baseline: 1.0837x; 1.0011x over previous
#include <cuda_runtime.h>
#include <cuda_fp16.h>
#include <cstdint>

// ===================== device scratch (allocation-free) =====================
__device__ __half g_xh[8192u * 1024u];
__device__ __half g_xl[8192u * 1024u];
__device__ __half g_hh[8192u * 4096u];   // [h1|h2] hi (fp16)
__device__ __half g_hl[8192u * 4096u];   // [h1|h2] lo (fp16)
__device__ __half g_B1h[4096u * 1024u];  // [W1_1|W2_1]^T hi  [4096,1024]
__device__ __half g_B1l[4096u * 1024u];
__device__ __half g_B2h[256u * 4096u];   // W2_2^T  [256,4096]
__device__ __half g_B2l[256u * 4096u];
__device__ __half g_BLh[64u * 2048u];    // W1_2^T  [64,2048]
__device__ __half g_BLl[64u * 2048u];
__device__ float g_part2[4u * 8192u * 256u];  // L2 split-K partials
__device__ float g_part1[2u * 8192u * 64u];   // L1 split-K partials

// ===================== PTX helpers (plain sm_80-era PTX only) ==============
__device__ __forceinline__ uint32_t s2u(const void* p) {
    uint32_t a;
    asm("{ .reg .u64 t; cvta.to.shared.u64 t, %1; cvt.u32.u64 %0, t; }" : "=r"(a) : "l"(p));
    return a;
}
__device__ __forceinline__ void cpa16(uint32_t d, const void* s) {
    asm volatile("cp.async.cg.shared.global [%0], [%1], 16;" :: "r"(d), "l"(s));
}
__device__ __forceinline__ void ldsm4(uint32_t* r, uint32_t a) {
    asm volatile("ldmatrix.sync.aligned.m8n8.x4.shared.b16 {%0,%1,%2,%3}, [%4];"
                 : "=r"(r[0]), "=r"(r[1]), "=r"(r[2]), "=r"(r[3]) : "r"(a));
}
__device__ __forceinline__ void mma16816(float* c, const uint32_t* a, const uint32_t* b) {
    asm volatile(
        "mma.sync.aligned.m16n8k16.row.col.f32.f16.f16.f32 "
        "{%0,%1,%2,%3}, {%4,%5,%6,%7}, {%8,%9}, {%0,%1,%2,%3};"
        : "+f"(c[0]), "+f"(c[1]), "+f"(c[2]), "+f"(c[3])
        : "r"(a[0]), "r"(a[1]), "r"(a[2]), "r"(a[3]), "r"(b[0]), "r"(b[1]));
}
// 64B rows, XOR-swizzled 16B chunks: conflict-free for ldmatrix + cp.async
__device__ __forceinline__ int swz(int row, int kc) {
    return row * 64 + (((kc ^ ((row >> 1) & 3)) & 3) << 4);
}

// ===================== split-fp16 HMMA GEMM =====================
// C[M,Ntot] = (Ah+Al)[M,K] @ (Bh+Bl)^T, 3 terms (drop Al*Bl), all f32 accum.
// BM=128, BK=32. 128 threads = 4 warps (2m x 2n); warp tile 64 x (BN/2).
// 3-stage cp.async pipeline, 2 CTAs/SM.
// split-K via gridDim.z: z-th CTA handles its kt slice; MODE 0 writes raw fp32
// partials to Cf + z*8192*Ntot. MODE 1 (gridDim.z==1): bias+relu, hi/lo fp16
// out; bias chosen from biasA (n0<2048) or biasB.
template <int MODE, int BN>
__global__ __launch_bounds__(128, 2) void hgemm3(
    const __half* __restrict__ Ah, const __half* __restrict__ Al, int lda,
    const __half* __restrict__ Bh, const __half* __restrict__ Bl, int ldb,
    int kc_total,
    const float* __restrict__ biasA, const float* __restrict__ biasB,
    float* __restrict__ Cf, __half* __restrict__ Chh, __half* __restrict__ Chl,
    int Ntot)
{
    constexpr int BM = 128;
    constexpr int NF   = BN / 16;                 // n-frags per warp
    constexpr int ASTB = BM * 64;                 // bytes per A sub-tile (8 KB)
    constexpr int BSTB = BN * 64;                 // bytes per B sub-tile
    constexpr int STAGEB = 2 * ASTB + 2 * BSTB;

    extern __shared__ __align__(16) char smem[];
    const uint32_t sb = s2u(smem);

    const int tid = threadIdx.x, lane = tid & 31, wid = tid >> 5;
    const int wm = wid & 1, wn = wid >> 1;        // 2x2 warp grid
    const int m0 = blockIdx.y * BM, n0 = blockIdx.x * BN;

    // split-K slice
    const int ns = gridDim.z, z = blockIdx.z;
    const int kbase = kc_total / ns, krem = kc_total % ns;
    const int KC   = kbase + (z < krem);
    const int kbeg = z * kbase + (z < krem ? z : krem);
    if (MODE == 0) Cf += (size_t)z * 8192u * (size_t)Ntot;

    auto load_tile = [&](int kt, int s) {
        const int k0 = (kbeg + kt) << 5;
        const uint32_t d = sb + (uint32_t)s * STAGEB;
#pragma unroll
        for (int i = 0; i < 4; i++) {
            int c = i * 128 + tid, r = c >> 2, kc = c & 3;
            cpa16(d + swz(r, kc), Ah + (size_t)(m0 + r) * lda + k0 + kc * 8);
        }
#pragma unroll
        for (int i = 0; i < 4; i++) {
            int c = i * 128 + tid, r = c >> 2, kc = c & 3;
            cpa16(d + ASTB + swz(r, kc), Al + (size_t)(m0 + r) * lda + k0 + kc * 8);
        }
#pragma unroll
        for (int i = 0; i < BN / 32; i++) {
            int c = i * 128 + tid, r = c >> 2, kc = c & 3;
            cpa16(d + 2 * ASTB + swz(r, kc), Bh + (size_t)(n0 + r) * ldb + k0 + kc * 8);
        }
#pragma unroll
        for (int i = 0; i < BN / 32; i++) {
            int c = i * 128 + tid, r = c >> 2, kc = c & 3;
            cpa16(d + 2 * ASTB + BSTB + swz(r, kc), Bl + (size_t)(n0 + r) * ldb + k0 + kc * 8);
        }
        asm volatile("cp.async.commit_group;" ::: "memory");
    };

    float acc[4][NF][4];
#pragma unroll
    for (int i = 0; i < 4; i++)
#pragma unroll
        for (int j = 0; j < NF; j++)
#pragma unroll
            for (int k = 0; k < 4; k++) acc[i][j][k] = 0.f;

    // per-thread ldmatrix row/k mapping
    const int arow = wm * 64 + (lane & 7) + ((lane & 8) ? 8 : 0);
    const int akc0 = (lane >> 4) & 1;
    const int brow = wn * (BN / 2) + (lane & 7) + ((lane & 16) ? 8 : 0);
    const int bkc0 = (lane >> 3) & 1;

    load_tile(0, 0);
    load_tile(1, 1);

    for (int kt = 0; kt < KC; kt++) {
        asm volatile("cp.async.wait_group 1;" ::: "memory");
        __syncthreads();
        if (kt + 2 < KC) load_tile(kt + 2, (kt + 2) % 3);
        else asm volatile("cp.async.commit_group;" ::: "memory");

        const uint32_t st = sb + (uint32_t)(kt % 3) * STAGEB;
#pragma unroll
        for (int ks = 0; ks < 2; ks++) {
            uint32_t Af[4][4], Bhf[NF][2], Blf[NF][2];
            const int akc = ks * 2 + akc0;
            const int bkc = ks * 2 + bkc0;
#pragma unroll
            for (int mf = 0; mf < 4; mf++)
                ldsm4(Af[mf], st + swz(arow + mf * 16, akc));
#pragma unroll
            for (int np = 0; np < NF / 2; np++)
                ldsm4(&Bhf[2 * np][0], st + 2 * ASTB + swz(brow + np * 16, bkc));
#pragma unroll
            for (int mf = 0; mf < 4; mf++)
#pragma unroll
                for (int nf = 0; nf < NF; nf++)
                    mma16816(acc[mf][nf], Af[mf], Bhf[nf]);     // Ah * Bh
#pragma unroll
            for (int np = 0; np < NF / 2; np++)
                ldsm4(&Blf[2 * np][0], st + 2 * ASTB + BSTB + swz(brow + np * 16, bkc));
#pragma unroll
            for (int mf = 0; mf < 4; mf++)
#pragma unroll
                for (int nf = 0; nf < NF; nf++)
                    mma16816(acc[mf][nf], Af[mf], Blf[nf]);     // Ah * Bl
#pragma unroll
            for (int mf = 0; mf < 4; mf++)
                ldsm4(Af[mf], st + ASTB + swz(arow + mf * 16, akc));
#pragma unroll
            for (int mf = 0; mf < 4; mf++)
#pragma unroll
                for (int nf = 0; nf < NF; nf++)
                    mma16816(acc[mf][nf], Af[mf], Bhf[nf]);     // Al * Bh
        }
    }

    // ---------------- epilogue ----------------
    const int r0 = m0 + wm * 64 + (lane >> 2);
    const int c0 = n0 + wn * (BN / 2) + ((lane & 3) << 1);
    const float* bp = (MODE == 1) ? ((n0 < 2048) ? biasA + n0 : biasB + (n0 - 2048))
                                  : nullptr;
#pragma unroll
    for (int mf = 0; mf < 4; mf++) {
#pragma unroll
        for (int nf = 0; nf < NF; nf++) {
            const int row = r0 + mf * 16, col = c0 + nf * 8;
            if (MODE == 0) {
                *reinterpret_cast<float2*>(&Cf[(size_t)row * Ntot + col]) =
                    make_float2(acc[mf][nf][0], acc[mf][nf][1]);
                *reinterpret_cast<float2*>(&Cf[(size_t)(row + 8) * Ntot + col]) =
                    make_float2(acc[mf][nf][2], acc[mf][nf][3]);
            } else {
                const float b0 = bp[col - n0], b1 = bp[col - n0 + 1];
                float v00 = fmaxf(acc[mf][nf][0] + b0, 0.f);
                float v01 = fmaxf(acc[mf][nf][1] + b1, 0.f);
                float v10 = fmaxf(acc[mf][nf][2] + b0, 0.f);
                float v11 = fmaxf(acc[mf][nf][3] + b1, 0.f);
                __half h00 = __float2half_rn(v00), h01 = __float2half_rn(v01);
                __half h10 = __float2half_rn(v10), h11 = __float2half_rn(v11);
                *reinterpret_cast<__half2*>(&Chh[(size_t)row * Ntot + col]) = __halves2half2(h00, h01);
                *reinterpret_cast<__half2*>(&Chh[(size_t)(row + 8) * Ntot + col]) = __halves2half2(h10, h11);
                __half l00 = __float2half_rn(v00 - __half2float(h00));
                __half l01 = __float2half_rn(v01 - __half2float(h01));
                __half l10 = __float2half_rn(v10 - __half2float(h10));
                __half l11 = __float2half_rn(v11 - __half2float(h11));
                *reinterpret_cast<__half2*>(&Chl[(size_t)row * Ntot + col]) = __halves2half2(l00, l01);
                *reinterpret_cast<__half2*>(&Chl[(size_t)(row + 8) * Ntot + col]) = __halves2half2(l10, l11);
            }
        }
    }
}

// ===================== conversion kernels =====================
// vectorized: 4 fp32 -> 4 hi fp16 + 4 lo fp16 per thread
__global__ void split_cvt4(const float4* __restrict__ s, __half2* __restrict__ oh,
                           __half2* __restrict__ ol, int n4) {
    int i = blockIdx.x * 256 + threadIdx.x;
    if (i < n4) {
        float4 v = s[i];
        __half h0 = __float2half_rn(v.x), h1 = __float2half_rn(v.y);
        __half h2 = __float2half_rn(v.z), h3 = __float2half_rn(v.w);
        oh[2 * i]     = __halves2half2(h0, h1);
        oh[2 * i + 1] = __halves2half2(h2, h3);
        __half l0 = __float2half_rn(v.x - __half2float(h0));
        __half l1 = __float2half_rn(v.y - __half2float(h1));
        __half l2 = __float2half_rn(v.z - __half2float(h2));
        __half l3 = __float2half_rn(v.w - __half2float(h3));
        ol[2 * i]     = __halves2half2(l0, l1);
        ol[2 * i + 1] = __halves2half2(l2, l3);
    }
}

// transpose+split one 32x32 tile: src [R,C] fp32 -> dst[c * ldd + r] fp16 hi/lo
__device__ __forceinline__ void trans_tile(
    const float* __restrict__ src, int C, int ldd, int r0, int c0,
    __half* __restrict__ oh, __half* __restrict__ ol,
    int x, int y)
{
    __shared__ float t[32][33];
#pragma unroll
    for (int i = 0; i < 32; i += 8)
        t[y + i][x] = src[(size_t)(r0 + y + i) * C + c0 + x];
    __syncthreads();
#pragma unroll
    for (int i = 0; i < 32; i += 8) {
        float v = t[x][y + i];
        __half h = __float2half_rn(v);
        size_t o = (size_t)(c0 + y + i) * ldd + r0 + x;
        oh[o] = h;
        ol[o] = __float2half_rn(v - __half2float(h));
    }
}

// merged first-layer transposes: W1_1 and W2_1, both [1024,2048] -> [2048,1024],
// 2048 tiles each; flat grid of 4096 blocks.
__global__ void trans_first(const float* __restrict__ W1_1,
                            const float* __restrict__ W2_1,
                            __half* __restrict__ B1h, __half* __restrict__ B1l) {
    int b = blockIdx.x;
    const float* src = W1_1;
    __half* oh = B1h;
    __half* ol = B1l;
    if (b >= 2048) {
        b -= 2048;
        src = W2_1;
        oh = B1h + (size_t)2048 * 1024;
        ol = B1l + (size_t)2048 * 1024;
    }
    int bx = b & 63, by = b >> 6;   // 64 col-tiles x 32 row-tiles
    trans_tile(src, 2048, 1024, by * 32, bx * 32, oh, ol, threadIdx.x, threadIdx.y);
}

// merged head-weight transposes: W2_2 [4096,256]->B2 [256,4096] (1024 tiles),
// then W1_2 [2048,64]->BL [64,2048] (128 tiles). flat grid of 1152 blocks.
__global__ void trans_heads(const float* __restrict__ W2_2, __half* __restrict__ B2h,
                            __half* __restrict__ B2l,
                            const float* __restrict__ W1_2, __half* __restrict__ BLh,
                            __half* __restrict__ BLl) {
    int b = blockIdx.x;
    if (b < 1024) {
        int bx = b & 7, by = b >> 3;         // 8 col-tiles x 128 row-tiles
        trans_tile(W2_2, 256, 4096, by * 32, bx * 32, B2h, B2l,
                   threadIdx.x, threadIdx.y);
    } else {
        b -= 1024;
        int bx = b & 1, by = b >> 1;         // 2 col-tiles x 64 row-tiles
        trans_tile(W1_2, 64, 2048, by * 32, bx * 32, BLh, BLl,
                   threadIdx.x, threadIdx.y);
    }
}

// ==== fused heads: split-K reduce + bias + relu + L1 softmax/argmax + L2 ====
// One block per row (256 threads). P2: 4 partials [8192,256]; P1: 2 partials [8192,64].
__global__ __launch_bounds__(256) void heads(
    const float* __restrict__ P2, const float* __restrict__ P1,
    const float* __restrict__ b2_2, const float* __restrict__ b1_2,
    const int* __restrict__ child_parent,
    float* __restrict__ outL1, float* __restrict__ outL2)
{
    constexpr size_t S2 = (size_t)8192 * 256;
    constexpr size_t S1 = (size_t)8192 * 64;
    const int row = blockIdx.x;
    const int j = threadIdx.x;
    const int lane = j & 31, w = j >> 5;

    // L2 logits (fixed-order reduce: deterministic)
    const size_t b2 = (size_t)row * 256 + j;
    float v2 = P2[b2] + P2[S2 + b2] + P2[2 * S2 + b2] + P2[3 * S2 + b2] + b2_2[j];
    v2 = fmaxf(v2, 0.f);

    __shared__ float l1v[64];
    __shared__ float red[8];
    __shared__ int sparent;

    if (j < 64) {
        const size_t b1 = (size_t)row * 64 + j;
        float v1 = P1[b1] + P1[S1 + b1] + b1_2[j];
        l1v[j] = fmaxf(v1, 0.f);
    }
    __syncthreads();

    // warp 0: L1 softmax + argmax (first-index tie-break)
    if (w == 0) {
        float v0 = l1v[lane], v1 = l1v[lane + 32];
        float bv; int bi;
        if (v0 >= v1) { bv = v0; bi = lane; } else { bv = v1; bi = lane + 32; }
#pragma unroll
        for (int off = 16; off; off >>= 1) {
            float ov = __shfl_xor_sync(0xFFFFFFFFu, bv, off);
            int   oi = __shfl_xor_sync(0xFFFFFFFFu, bi, off);
            if (ov > bv || (ov == bv && oi < bi)) { bv = ov; bi = oi; }
        }
        float e0 = __expf(v0 - bv), e1 = __expf(v1 - bv);
        float s = e0 + e1;
#pragma unroll
        for (int off = 16; off; off >>= 1)
            s += __shfl_xor_sync(0xFFFFFFFFu, s, off);
        float inv = 1.f / s;
        outL1[(size_t)row * 64 + lane]      = e0 * inv;
        outL1[(size_t)row * 64 + 32 + lane] = e1 * inv;
        if (lane == 0) sparent = bi;
    }
    __syncthreads();

    // L2 masked softmax over 256
    const int p = sparent;
    float v = (child_parent[j] == p) ? v2 : v2 - 10000.0f;

    float m = v;
#pragma unroll
    for (int off = 16; off; off >>= 1)
        m = fmaxf(m, __shfl_xor_sync(0xFFFFFFFFu, m, off));
    if (lane == 0) red[w] = m;
    __syncthreads();
    float bm = red[0];
#pragma unroll
    for (int i = 1; i < 8; i++) bm = fmaxf(bm, red[i]);
    __syncthreads();

    float e = __expf(v - bm);
    float s = e;
#pragma unroll
    for (int off = 16; off; off >>= 1)
        s += __shfl_xor_sync(0xFFFFFFFFu, s, off);
    if (lane == 0) red[w] = s;
    __syncthreads();
    float bs = 0.f;
#pragma unroll
    for (int i = 0; i < 8; i++) bs += red[i];

    outL2[(size_t)row * 256 + j] = e / bs;
}

// ===================== launch =====================
extern "C" void kernel_launch(void* const* d_in, const int* in_sizes, int n_in,
                              void* d_out, int out_size)
{
    const float* x    = (const float*)d_in[0];
    const float* W1_1 = (const float*)d_in[1];
    const float* b1_1 = (const float*)d_in[2];
    const float* W1_2 = (const float*)d_in[3];
    const float* b1_2 = (const float*)d_in[4];
    const float* W2_1 = (const float*)d_in[5];
    const float* b2_1 = (const float*)d_in[6];
    const float* W2_2 = (const float*)d_in[7];
    const float* b2_2 = (const float*)d_in[8];
    const int* child_parent = (const int*)d_in[9];

    float* out   = (float*)d_out;
    float* outL1 = out;
    float* outL2 = out + (size_t)8192 * 64;

    __half *xh, *xl, *hh, *hl, *B1h, *B1l, *B2h, *B2l, *BLh, *BLl;
    float *part2, *part1;
    cudaGetSymbolAddress((void**)&xh,  g_xh);
    cudaGetSymbolAddress((void**)&xl,  g_xl);
    cudaGetSymbolAddress((void**)&hh,  g_hh);
    cudaGetSymbolAddress((void**)&hl,  g_hl);
    cudaGetSymbolAddress((void**)&B1h, g_B1h);
    cudaGetSymbolAddress((void**)&B1l, g_B1l);
    cudaGetSymbolAddress((void**)&B2h, g_B2h);
    cudaGetSymbolAddress((void**)&B2l, g_B2l);
    cudaGetSymbolAddress((void**)&BLh, g_BLh);
    cudaGetSymbolAddress((void**)&BLl, g_BLl);
    cudaGetSymbolAddress((void**)&part2, g_part2);
    cudaGetSymbolAddress((void**)&part1, g_part1);

    constexpr int SMEM128 = 3 * (2 * 128 * 64 + 2 * 128 * 64);  // 98304
    constexpr int SMEM64  = 3 * (2 * 128 * 64 + 2 * 64 * 64);   // 73728
    cudaFuncSetAttribute(hgemm3<1, 128>, cudaFuncAttributeMaxDynamicSharedMemorySize, SMEM128);
    cudaFuncSetAttribute(hgemm3<0, 128>, cudaFuncAttributeMaxDynamicSharedMemorySize, SMEM128);
    cudaFuncSetAttribute(hgemm3<0, 64>,  cudaFuncAttributeMaxDynamicSharedMemorySize, SMEM64);

    // 0) x -> fp16 hi/lo (vectorized)
    split_cvt4<<<(8192 * 1024 / 4) / 256, 256>>>(
        (const float4*)x, (__half2*)xh, (__half2*)xl, 8192 * 1024 / 4);
    // 1) first-layer weights -> transposed fp16 hi/lo (merged, one launch)
    trans_first<<<4096, dim3(32, 8)>>>(W1_1, W2_1, B1h, B1l);
    // 2) merged head-weight transposes (independent of stage-1)
    trans_heads<<<1152, dim3(32, 8)>>>(W2_2, B2h, B2l, W1_2, BLh, BLl);
    // 3) stage-1 GEMM (launch index 3 -> lands in ncu's captured slot)
    hgemm3<1, 128><<<dim3(32, 64, 1), 128, SMEM128>>>(
        xh, xl, 1024, B1h, B1l, 1024, 32, b1_1, b2_1, nullptr, hh, hl, 4096);
    // 4) L2 logits GEMM, split-K=4 -> raw fp32 partials  (N=256, K=4096)
    hgemm3<0, 128><<<dim3(2, 64, 4), 128, SMEM128>>>(
        hh, hl, 4096, B2h, B2l, 4096, 128, nullptr, nullptr, part2, nullptr, nullptr, 256);
    // 5) L1 head GEMM, split-K=2 -> raw fp32 partials  (N=64, K=2048, h1 only)
    hgemm3<0, 64><<<dim3(1, 64, 2), 128, SMEM64>>>(
        hh, hl, 4096, BLh, BLl, 2048, 64, nullptr, nullptr, part1, nullptr, nullptr, 64);
    // 6) fused heads: reduce + bias + relu + L1 softmax/argmax + L2 masked softmax
    heads<<<8192, 256>>>(part2, part1, b2_2, b1_2, child_parent, outL1, outL2);
}